// round 17
// baseline (speedup 1.0000x reference)
#include <cuda_runtime.h>
#include <cuda_bf16.h>
#include <cuda_fp16.h>
#include <math.h>
#include <cstdint>

#define NUM_B 2
#define NUM_N 2048
#define NUM_C 1024
#define NUM_H 16
#define HD    64
#define MTOT  (NUM_B*NUM_N)      /* 4096 */

// ---------------------------------------------------------------------------
// Scratch (allocation-free: __device__ globals)
// ---------------------------------------------------------------------------
__device__ __nv_bfloat16 g_qh[NUM_B*NUM_H*NUM_N*HD];  // LN'd q (x0.125) hi/lo
__device__ __nv_bfloat16 g_ql[NUM_B*NUM_H*NUM_N*HD];
__device__ __nv_bfloat16 g_kh[NUM_B*NUM_H*NUM_N*HD];  // LN'd k hi/lo
__device__ __nv_bfloat16 g_kl[NUM_B*NUM_H*NUM_N*HD];
__device__ __half        g_vh[NUM_B*NUM_H*NUM_N*HD];  // V fp16

// split-bf16 copies (hi/lo) for tensor-core GEMMs
__device__ __nv_bfloat16 g_xh [MTOT*NUM_C];
__device__ __nv_bfloat16 g_xl [MTOT*NUM_C];
__device__ __nv_bfloat16 g_wqh[3*NUM_C*NUM_C];
__device__ __nv_bfloat16 g_wql[3*NUM_C*NUM_C];
__device__ __nv_bfloat16 g_aoh[MTOT*NUM_C];    // attention out hi/lo
__device__ __nv_bfloat16 g_aol[MTOT*NUM_C];
__device__ __nv_bfloat16 g_wph[NUM_C*NUM_C];
__device__ __nv_bfloat16 g_wpl[NUM_C*NUM_C];

// ---------------------------------------------------------------------------
// PTX helpers
// ---------------------------------------------------------------------------
__device__ __forceinline__ uint32_t smem_to_u32(const void* p) {
    uint32_t a;
    asm("{ .reg .u64 t; cvta.to.shared.u64 t, %1; cvt.u32.u64 %0, t; }" : "=r"(a) : "l"(p));
    return a;
}
__device__ __forceinline__ void mma16816(float* d, const uint32_t* a, const uint32_t* b) {
    asm volatile(
        "mma.sync.aligned.m16n8k16.row.col.f32.bf16.bf16.f32 "
        "{%0,%1,%2,%3}, {%4,%5,%6,%7}, {%8,%9}, {%0,%1,%2,%3};"
        : "+f"(d[0]), "+f"(d[1]), "+f"(d[2]), "+f"(d[3])
        : "r"(a[0]), "r"(a[1]), "r"(a[2]), "r"(a[3]), "r"(b[0]), "r"(b[1]));
}
__device__ __forceinline__ void mma16816h(float* d, const uint32_t* a, const uint32_t* b) {
    asm volatile(
        "mma.sync.aligned.m16n8k16.row.col.f32.f16.f16.f32 "
        "{%0,%1,%2,%3}, {%4,%5,%6,%7}, {%8,%9}, {%0,%1,%2,%3};"
        : "+f"(d[0]), "+f"(d[1]), "+f"(d[2]), "+f"(d[3])
        : "r"(a[0]), "r"(a[1]), "r"(a[2]), "r"(a[3]), "r"(b[0]), "r"(b[1]));
}
__device__ __forceinline__ void ldsm4(uint32_t* r, uint32_t a) {
    asm volatile("ldmatrix.sync.aligned.m8n8.x4.shared.b16 {%0,%1,%2,%3}, [%4];"
        : "=r"(r[0]), "=r"(r[1]), "=r"(r[2]), "=r"(r[3]) : "r"(a));
}
__device__ __forceinline__ void ldsm4t(uint32_t* r, uint32_t a) {
    asm volatile("ldmatrix.sync.aligned.m8n8.x4.trans.shared.b16 {%0,%1,%2,%3}, [%4];"
        : "=r"(r[0]), "=r"(r[1]), "=r"(r[2]), "=r"(r[3]) : "r"(a));
}
#define CP16(dst, src) \
    asm volatile("cp.async.cg.shared.global [%0], [%1], 16;" :: "r"(dst), "l"(src))
#define CP_COMMIT() asm volatile("cp.async.commit_group;" ::: "memory")
#define CP_WAIT(n)  asm volatile("cp.async.wait_group %0;" :: "n"(n) : "memory")

__device__ __forceinline__ uint32_t pack_h2(float a, float b) {
    __half2 h = __floats2half2_rn(a, b);
    return *reinterpret_cast<uint32_t*>(&h);
}
__device__ __forceinline__ uint32_t pack_bf2(float a, float b) {
    __nv_bfloat162 h(__float2bfloat16(a), __float2bfloat16(b));
    return *reinterpret_cast<uint32_t*>(&h);
}
// swizzled byte offset within a 128-row x 128B tile
__device__ __forceinline__ uint32_t swz(uint32_t row, uint32_t chunk) {
    return row * 128u + ((chunk ^ (row & 7u)) * 16u);
}

// ---------------------------------------------------------------------------
// Kernel 0: fp32 -> (bf16 hi, bf16 lo) split conversion, 4 elems/thread.
// ---------------------------------------------------------------------------
struct __align__(8) bf4 { __nv_bfloat16 a, b, c, d; };

__global__ __launch_bounds__(256) void split_conv(const float* __restrict__ s,
                                                  __nv_bfloat16* __restrict__ hi,
                                                  __nv_bfloat16* __restrict__ lo,
                                                  int n4) {
    int i = blockIdx.x * blockDim.x + threadIdx.x;
    if (i >= n4) return;
    float4 v = reinterpret_cast<const float4*>(s)[i];
    __nv_bfloat16 h0 = __float2bfloat16(v.x);
    __nv_bfloat16 h1 = __float2bfloat16(v.y);
    __nv_bfloat16 h2 = __float2bfloat16(v.z);
    __nv_bfloat16 h3 = __float2bfloat16(v.w);
    __nv_bfloat16 l0 = __float2bfloat16(v.x - __bfloat162float(h0));
    __nv_bfloat16 l1 = __float2bfloat16(v.y - __bfloat162float(h1));
    __nv_bfloat16 l2 = __float2bfloat16(v.z - __bfloat162float(h2));
    __nv_bfloat16 l3 = __float2bfloat16(v.w - __bfloat162float(h3));
    bf4 hh = {h0, h1, h2, h3};
    bf4 ll = {l0, l1, l2, l3};
    reinterpret_cast<bf4*>(hi)[i] = hh;
    reinterpret_cast<bf4*>(lo)[i] = ll;
}

// ---------------------------------------------------------------------------
// Kernel 1/3: mma.sync bf16-split GEMM.  Block 128x128, BK=32, 8 warps.
// Merged hi/lo tiles (128B rows, XOR swizzle) -> 3-stage cp.async pipeline,
// 2 CTAs/SM.  EPI=0: q/k LN'd -> bf16 hi/lo; v -> fp16.  EPI=1: out + bias.
// Stage layout: A tile 16KB (chunks 0-3 hi k0..31, 4-7 lo), B tile 16KB.
// ---------------------------------------------------------------------------
#define TILE_G   16384                    /* 128 rows x 128 B */
#define STAGE_B  (2*TILE_G)               /* 32768 B */
#define NSTAGE   3
#define GEMM_SMEM (NSTAGE*STAGE_B)        /* 98304 B */

template<int EPI>
__global__ __launch_bounds__(256, 2) void mma_gemm(const __nv_bfloat16* __restrict__ Ah,
                                                   const __nv_bfloat16* __restrict__ Al,
                                                   const __nv_bfloat16* __restrict__ Bh,
                                                   const __nv_bfloat16* __restrict__ Bl,
                                                   const float* __restrict__ bias,
                                                   float* __restrict__ outp,
                                                   const float* __restrict__ q_gamma,
                                                   const float* __restrict__ q_beta,
                                                   const float* __restrict__ k_gamma,
                                                   const float* __restrict__ k_beta) {
    extern __shared__ __nv_bfloat16 smem[];
    const uint32_t sb = smem_to_u32(smem);
    const int tid  = threadIdx.x;
    const int wid  = tid >> 5, lane = tid & 31;
    const int wm   = wid >> 1;
    const int wn   = wid & 1;
    const int g    = lane >> 2;
    const int tg   = lane & 3;
    const int bm   = blockIdx.y * 128;
    const int bn   = blockIdx.x * 128;

    // loader: row = tid>>1; even thread -> hi chunks 0-3, odd -> lo chunks 4-7
    const uint32_t lrow = (uint32_t)(tid >> 1);
    const uint32_t lch0 = (uint32_t)((tid & 1) * 4);
    const __nv_bfloat16* srcA = ((tid & 1) ? Al : Ah) + (size_t)(bm + lrow) * NUM_C;
    const __nv_bfloat16* srcB = ((tid & 1) ? Bl : Bh) + (size_t)(bn + lrow) * NUM_C;

#define GISSUE(s, c) do {                                                      \
        const uint32_t _base = sb + (uint32_t)(s) * STAGE_B;                   \
        const int _k0 = (c) * 32;                                              \
        _Pragma("unroll")                                                      \
        for (int j = 0; j < 4; j++) {                                          \
            const uint32_t ch = lch0 + j;                                      \
            const uint32_t so = swz(lrow, ch);                                 \
            CP16(_base + so,          srcA + _k0 + j*8);                       \
            CP16(_base + TILE_G + so, srcB + _k0 + j*8);                       \
        }                                                                      \
    } while (0)

    // ldmatrix lane addressing (logical row / chunk; swizzle applied at use)
    const uint32_t arow = (uint32_t)(wm*32 + ((lane>>3)&1)*8 + (lane&7));
    const uint32_t ach  = (uint32_t)(lane>>4);             // + 2*ks (hi), +4 (lo)
    const uint32_t brow = (uint32_t)(wn*64 + ((lane>>4)&1)*8 + (lane&7));
    const uint32_t bch  = (uint32_t)((lane>>3)&1);         // + 2*ks (hi), +4 (lo)

    float acc[2][8][4];
#pragma unroll
    for (int i = 0; i < 2; i++)
#pragma unroll
        for (int j = 0; j < 8; j++)
#pragma unroll
            for (int t = 0; t < 4; t++) acc[i][j][t] = 0.0f;

    GISSUE(0, 0); CP_COMMIT();
    GISSUE(1, 1); CP_COMMIT();

    const int NCH = NUM_C/32;
    for (int c = 0; c < NCH; c++) {
        if (c + 1 < NCH) { CP_WAIT(1); } else { CP_WAIT(0); }
        __syncthreads();
        if (c + 2 < NCH) {
            GISSUE((c + 2) % NSTAGE, c + 2);
            CP_COMMIT();
        }

        const uint32_t stB = sb + (uint32_t)(c % NSTAGE) * STAGE_B;
#pragma unroll
        for (int ks = 0; ks < 2; ks++) {
            uint32_t fah[2][4], fal[2][4];
#pragma unroll
            for (int mf = 0; mf < 2; mf++) {
                const uint32_t r = arow + mf*16;
                ldsm4(fah[mf], stB + swz(r, 2*ks + ach));
                ldsm4(fal[mf], stB + swz(r, 4 + 2*ks + ach));
            }
#pragma unroll
            for (int p = 0; p < 4; p++) {
                const uint32_t r = brow + p*16;
                uint32_t bh4[4], bl4[4];
                ldsm4(bh4, stB + TILE_G + swz(r, 2*ks + bch));
                ldsm4(bl4, stB + TILE_G + swz(r, 4 + 2*ks + bch));
#pragma unroll
                for (int mf = 0; mf < 2; mf++) {
                    mma16816(acc[mf][2*p],   fah[mf], bh4);
                    mma16816(acc[mf][2*p],   fah[mf], bl4);
                    mma16816(acc[mf][2*p],   fal[mf], bh4);
                    mma16816(acc[mf][2*p+1], fah[mf], bh4 + 2);
                    mma16816(acc[mf][2*p+1], fah[mf], bl4 + 2);
                    mma16816(acc[mf][2*p+1], fal[mf], bh4 + 2);
                }
            }
        }
        __syncthreads();
    }
#undef GISSUE

    if (EPI == 0) {
        const int n0 = bn + wn*64;
        const int which = n0 >> 10;
        const int h = (n0 & 1023) >> 6;
        if (which < 2) {
            // fused LayerNorm over the 64-col head row (held by the tg-quad)
            __nv_bfloat16* dh = (which == 0) ? g_qh : g_kh;
            __nv_bfloat16* dl = (which == 0) ? g_ql : g_kl;
            const float* gam = (which == 0) ? q_gamma : k_gamma;
            const float* bet = (which == 0) ? q_beta  : k_beta;
            const float scl = (which == 0) ? 0.125f : 1.0f;
            float gv[16], bv[16];
#pragma unroll
            for (int nf = 0; nf < 8; nf++) {
                float2 g2 = *reinterpret_cast<const float2*>(&gam[nf*8 + tg*2]);
                float2 b2 = *reinterpret_cast<const float2*>(&bet[nf*8 + tg*2]);
                gv[2*nf] = g2.x; gv[2*nf+1] = g2.y;
                bv[2*nf] = b2.x * scl; bv[2*nf+1] = b2.y * scl;
            }
#pragma unroll
            for (int mf = 0; mf < 2; mf++) {
#pragma unroll
                for (int half = 0; half < 2; half++) {
                    float s = 0.f, ss = 0.f;
#pragma unroll
                    for (int nf = 0; nf < 8; nf++) {
                        float v0 = acc[mf][nf][half*2], v1 = acc[mf][nf][half*2+1];
                        s += v0 + v1; ss += v0*v0 + v1*v1;
                    }
                    s  += __shfl_xor_sync(0xffffffffu, s,  1);
                    s  += __shfl_xor_sync(0xffffffffu, s,  2);
                    ss += __shfl_xor_sync(0xffffffffu, ss, 1);
                    ss += __shfl_xor_sync(0xffffffffu, ss, 2);
                    float mu  = s * (1.0f/64.0f);
                    float var = ss * (1.0f/64.0f) - mu*mu;
                    float inv = rsqrtf(var + 1e-5f) * scl;
                    const int mrow = bm + wm*32 + mf*16 + g + half*8;
                    const size_t rb = (((size_t)((mrow >> 11) * NUM_H + h)) * NUM_N
                                       + (mrow & 2047)) * HD;
#pragma unroll
                    for (int nf = 0; nf < 8; nf++) {
                        float a0 = (acc[mf][nf][half*2]   - mu)*inv*gv[2*nf]   + bv[2*nf];
                        float a1 = (acc[mf][nf][half*2+1] - mu)*inv*gv[2*nf+1] + bv[2*nf+1];
                        uint32_t hh = pack_bf2(a0, a1);
                        __nv_bfloat162 hv = *reinterpret_cast<__nv_bfloat162*>(&hh);
                        *reinterpret_cast<uint32_t*>(&dh[rb + nf*8 + tg*2]) = hh;
                        *reinterpret_cast<uint32_t*>(&dl[rb + nf*8 + tg*2]) =
                            pack_bf2(a0 - __bfloat162float(hv.x), a1 - __bfloat162float(hv.y));
                    }
                }
            }
        } else {
#pragma unroll
            for (int mf = 0; mf < 2; mf++) {
#pragma unroll
                for (int half = 0; half < 2; half++) {
                    const int mrow = bm + wm*32 + mf*16 + g + half*8;
                    __half* dst = g_vh + (((size_t)((mrow >> 11) * NUM_H + h)) * NUM_N
                                          + (mrow & 2047)) * HD;
#pragma unroll
                    for (int nf = 0; nf < 8; nf++) {
                        *reinterpret_cast<uint32_t*>(dst + nf*8 + tg*2) =
                            pack_h2(acc[mf][nf][half*2], acc[mf][nf][half*2+1]);
                    }
                }
            }
        }
    } else {
#pragma unroll
        for (int mf = 0; mf < 2; mf++) {
#pragma unroll
            for (int half = 0; half < 2; half++) {
                const int mrow = bm + wm*32 + mf*16 + g + half*8;
                float* dst = outp + (size_t)mrow * NUM_C + bn + wn*64;
#pragma unroll
                for (int nf = 0; nf < 8; nf++) {
                    const int col = bn + wn*64 + nf*8 + tg*2;
                    *reinterpret_cast<float2*>(dst + nf*8 + tg*2) =
                        make_float2(acc[mf][nf][half*2] + bias[col],
                                    acc[mf][nf][half*2+1] + bias[col+1]);
                }
            }
        }
    }
}

// ---------------------------------------------------------------------------
// Kernel 2: tensor-core flash attention.  (unchanged from R16)
// ---------------------------------------------------------------------------
#define TILE_B   16384                     /* 128 rows x 128 B */
#define OFF_QH   0
#define OFF_QL   TILE_B
#define OFF_ST(s) (2*TILE_B + (s)*(3*TILE_B))   /* KH, KL, V per stage */
#define ATTN_SMEM (2*TILE_B + 2*3*TILE_B)  /* 131072 B */

__global__ __launch_bounds__(256) void attn_kernel(const unsigned char* __restrict__ mask) {
    extern __shared__ char asmem[];
    const uint32_t sb = smem_to_u32(asmem);

    const int bh = blockIdx.y;
    const int b  = bh >> 4;
    const int h  = bh & 15;
    const int q0 = blockIdx.x * 128;

    const __nv_bfloat16* Qhg = g_qh + ((size_t)bh*NUM_N + q0)*HD;
    const __nv_bfloat16* Qlg = g_ql + ((size_t)bh*NUM_N + q0)*HD;
    const __nv_bfloat16* Khg = g_kh + (size_t)bh*NUM_N*HD;
    const __nv_bfloat16* Klg = g_kl + (size_t)bh*NUM_N*HD;
    const __half*        Vg  = g_vh + (size_t)bh*NUM_N*HD;
    const unsigned char* mp  = mask + (size_t)b*NUM_N*NUM_N + (size_t)q0*NUM_N;

    const int tid  = threadIdx.x;
    const int wid  = tid >> 5, lane = tid & 31;
    const int g    = lane >> 2;
    const int tg   = lane & 3;
    const int wq   = wid * 16;

    const uint32_t lrow = (uint32_t)(tid >> 1);
    const uint32_t lch0 = (uint32_t)((tid & 1) * 4);

    const uint32_t aq_row = (uint32_t)(wq + ((lane>>3)&1)*8 + (lane&7));
    const uint32_t aq_ch  = (uint32_t)(lane>>4);
    const uint32_t kn_row = (uint32_t)(((lane>>4)&1)*8 + (lane&7));
    const uint32_t kn_ch  = (uint32_t)((lane>>3)&1);
    const uint32_t v_row  = (uint32_t)(((lane>>3)&1)*8 + (lane&7));
    const uint32_t v_ch   = (uint32_t)(lane>>4);

#pragma unroll
    for (int j = 0; j < 4; j++) {
        const uint32_t ch = lch0 + j;
        const uint32_t so = swz(lrow, ch);
        CP16(sb + OFF_QH + so, Qhg + lrow*HD + ch*8);
        CP16(sb + OFF_QL + so, Qlg + lrow*HD + ch*8);
    }
#define KVISSUE(s, kt) do {                                                    \
        const uint32_t _st = OFF_ST(s);                                        \
        const int _k0 = (kt) * 128;                                            \
        _Pragma("unroll")                                                      \
        for (int j = 0; j < 4; j++) {                                          \
            const uint32_t ch = lch0 + j;                                      \
            const uint32_t so = swz(lrow, ch);                                 \
            CP16(sb + _st + so,            Khg + (size_t)(_k0 + lrow)*HD + ch*8); \
            CP16(sb + _st + TILE_B + so,   Klg + (size_t)(_k0 + lrow)*HD + ch*8); \
            CP16(sb + _st + 2*TILE_B + so, Vg  + (size_t)(_k0 + lrow)*HD + ch*8); \
        }                                                                      \
    } while (0)
    KVISSUE(0, 0);
    CP_COMMIT();

    float m_i[2], l_i[2];
    float O[8][4];
    m_i[0] = m_i[1] = -3.402823466e38f;
    l_i[0] = l_i[1] = 0.0f;
#pragma unroll
    for (int dn = 0; dn < 8; dn++)
#pragma unroll
        for (int t = 0; t < 4; t++) O[dn][t] = 0.0f;

    for (int kt = 0; kt < NUM_N/128; kt++) {
        const int k0 = kt * 128;
        if (kt + 1 < NUM_N/128) {
            KVISSUE((kt + 1) & 1, kt + 1);
            CP_COMMIT();
            CP_WAIT(1);
        } else {
            CP_WAIT(0);
        }
        __syncthreads();
        const uint32_t st = OFF_ST(kt & 1);

        float S[16][4];
#pragma unroll
        for (int nf = 0; nf < 16; nf++)
#pragma unroll
            for (int t = 0; t < 4; t++) S[nf][t] = 0.0f;

#pragma unroll
        for (int ks = 0; ks < 4; ks++) {
            uint32_t ah[4], al[4];
            const uint32_t qo = swz(aq_row, 2*ks + aq_ch);
            ldsm4(ah, sb + OFF_QH + qo);
            ldsm4(al, sb + OFF_QL + qo);
#pragma unroll
            for (int p = 0; p < 8; p++) {
                const uint32_t ko = swz(kn_row + p*16, 2*ks + kn_ch);
                uint32_t kh4[4], kl4[4];
                ldsm4(kh4, sb + st + ko);
                ldsm4(kl4, sb + st + TILE_B + ko);
                mma16816(S[2*p],   ah, kh4);
                mma16816(S[2*p],   ah, kl4);
                mma16816(S[2*p],   al, kh4);
                mma16816(S[2*p+1], ah, kh4 + 2);
                mma16816(S[2*p+1], ah, kl4 + 2);
                mma16816(S[2*p+1], al, kh4 + 2);
            }
        }

        {
            const unsigned char* m0p = mp + (size_t)(wq + g)*NUM_N + k0;
            const unsigned char* m1p = m0p + 8*NUM_N;
#pragma unroll
            for (int nf = 0; nf < 16; nf++) {
                const int cb = nf*8 + tg*2;
                uchar2 ma = *reinterpret_cast<const uchar2*>(m0p + cb);
                uchar2 mb = *reinterpret_cast<const uchar2*>(m1p + cb);
                if (ma.x) S[nf][0] = -3.402823466e38f;
                if (ma.y) S[nf][1] = -3.402823466e38f;
                if (mb.x) S[nf][2] = -3.402823466e38f;
                if (mb.y) S[nf][3] = -3.402823466e38f;
            }
            float rm0 = S[0][0], rm1 = S[0][2];
#pragma unroll
            for (int nf = 0; nf < 16; nf++) {
                rm0 = fmaxf(rm0, fmaxf(S[nf][0], S[nf][1]));
                rm1 = fmaxf(rm1, fmaxf(S[nf][2], S[nf][3]));
            }
            rm0 = fmaxf(rm0, __shfl_xor_sync(0xffffffffu, rm0, 1));
            rm0 = fmaxf(rm0, __shfl_xor_sync(0xffffffffu, rm0, 2));
            rm1 = fmaxf(rm1, __shfl_xor_sync(0xffffffffu, rm1, 1));
            rm1 = fmaxf(rm1, __shfl_xor_sync(0xffffffffu, rm1, 2));
            float mn0 = fmaxf(m_i[0], rm0);
            float mn1 = fmaxf(m_i[1], rm1);
            float al0 = __expf(m_i[0] - mn0);
            float al1 = __expf(m_i[1] - mn1);
            float ps0 = 0.f, ps1 = 0.f;
#pragma unroll
            for (int nf = 0; nf < 16; nf++) {
                S[nf][0] = __expf(S[nf][0] - mn0);
                S[nf][1] = __expf(S[nf][1] - mn0);
                S[nf][2] = __expf(S[nf][2] - mn1);
                S[nf][3] = __expf(S[nf][3] - mn1);
                ps0 += S[nf][0] + S[nf][1];
                ps1 += S[nf][2] + S[nf][3];
            }
            ps0 += __shfl_xor_sync(0xffffffffu, ps0, 1);
            ps0 += __shfl_xor_sync(0xffffffffu, ps0, 2);
            ps1 += __shfl_xor_sync(0xffffffffu, ps1, 1);
            ps1 += __shfl_xor_sync(0xffffffffu, ps1, 2);
            l_i[0] = l_i[0]*al0 + ps0;
            l_i[1] = l_i[1]*al1 + ps1;
            m_i[0] = mn0; m_i[1] = mn1;
#pragma unroll
            for (int dn = 0; dn < 8; dn++) {
                O[dn][0] *= al0; O[dn][1] *= al0;
                O[dn][2] *= al1; O[dn][3] *= al1;
            }
        }

#pragma unroll
        for (int ks = 0; ks < 8; ks++) {
            uint32_t pa[4];
            pa[0] = pack_h2(S[2*ks  ][0], S[2*ks  ][1]);
            pa[1] = pack_h2(S[2*ks  ][2], S[2*ks  ][3]);
            pa[2] = pack_h2(S[2*ks+1][0], S[2*ks+1][1]);
            pa[3] = pack_h2(S[2*ks+1][2], S[2*ks+1][3]);
#pragma unroll
            for (int p = 0; p < 4; p++) {
                const uint32_t vo = swz(ks*16 + v_row, p*2 + v_ch);
                uint32_t vb[4];
                ldsm4t(vb, sb + st + 2*TILE_B + vo);
                mma16816h(O[2*p],   pa, vb);
                mma16816h(O[2*p+1], pa, vb + 2);
            }
        }
        __syncthreads();
    }
#undef KVISSUE

    {
        float inv0 = 1.0f / l_i[0];
        float inv1 = 1.0f / l_i[1];
        const size_t r0 = (size_t)(b*NUM_N + q0 + wq + g)     * NUM_C + h*HD;
        const size_t r1 = (size_t)(b*NUM_N + q0 + wq + g + 8) * NUM_C + h*HD;
#pragma unroll
        for (int dn = 0; dn < 8; dn++) {
            const int c = dn*8 + tg*2;
            {
                float o0 = O[dn][0]*inv0, o1 = O[dn][1]*inv0;
                uint32_t hh = pack_bf2(o0, o1);
                __nv_bfloat162 hv = *reinterpret_cast<__nv_bfloat162*>(&hh);
                *reinterpret_cast<uint32_t*>(&g_aoh[r0 + c]) = hh;
                *reinterpret_cast<uint32_t*>(&g_aol[r0 + c]) =
                    pack_bf2(o0 - __bfloat162float(hv.x), o1 - __bfloat162float(hv.y));
            }
            {
                float o0 = O[dn][2]*inv1, o1 = O[dn][3]*inv1;
                uint32_t hh = pack_bf2(o0, o1);
                __nv_bfloat162 hv = *reinterpret_cast<__nv_bfloat162*>(&hh);
                *reinterpret_cast<uint32_t*>(&g_aoh[r1 + c]) = hh;
                *reinterpret_cast<uint32_t*>(&g_aol[r1 + c]) =
                    pack_bf2(o0 - __bfloat162float(hv.x), o1 - __bfloat162float(hv.y));
            }
        }
    }
}

// ---------------------------------------------------------------------------
extern "C" void kernel_launch(void* const* d_in, const int* in_sizes, int n_in,
                              void* d_out, int out_size) {
    const float* x       = (const float*)d_in[0];
    const unsigned char* mask = (const unsigned char*)d_in[1];
    const float* w_qkv   = (const float*)d_in[2];
    const float* w_proj  = (const float*)d_in[3];
    const float* b_proj  = (const float*)d_in[4];
    const float* q_gamma = (const float*)d_in[5];
    const float* q_beta  = (const float*)d_in[6];
    const float* k_gamma = (const float*)d_in[7];
    const float* k_beta  = (const float*)d_in[8];
    float* out = (float*)d_out;

    cudaFuncSetAttribute(attn_kernel,  cudaFuncAttributeMaxDynamicSharedMemorySize, ATTN_SMEM);
    cudaFuncSetAttribute(mma_gemm<0>,  cudaFuncAttributeMaxDynamicSharedMemorySize, GEMM_SMEM);
    cudaFuncSetAttribute(mma_gemm<1>,  cudaFuncAttributeMaxDynamicSharedMemorySize, GEMM_SMEM);

    __nv_bfloat16 *xh, *xl, *wqh, *wql, *aoh, *aol, *wph, *wpl;
    cudaGetSymbolAddress((void**)&xh,  g_xh);  cudaGetSymbolAddress((void**)&xl,  g_xl);
    cudaGetSymbolAddress((void**)&wqh, g_wqh); cudaGetSymbolAddress((void**)&wql, g_wql);
    cudaGetSymbolAddress((void**)&aoh, g_aoh); cudaGetSymbolAddress((void**)&aol, g_aol);
    cudaGetSymbolAddress((void**)&wph, g_wph); cudaGetSymbolAddress((void**)&wpl, g_wpl);

    const int n4x  = MTOT*NUM_C/4;
    const int n4wq = 3*NUM_C*NUM_C/4;
    const int n4wp = NUM_C*NUM_C/4;
    split_conv<<<(n4x  + 255)/256, 256>>>(x,      xh,  xl,  n4x);
    split_conv<<<(n4wq + 255)/256, 256>>>(w_qkv,  wqh, wql, n4wq);
    split_conv<<<(n4wp + 255)/256, 256>>>(w_proj, wph, wpl, n4wp);

    // 1) QKV GEMM (fused q/k LayerNorm -> bf16 hi/lo; v -> fp16)
    mma_gemm<0><<<dim3(3*NUM_C/128, MTOT/128), 256, GEMM_SMEM>>>(
        xh, xl, wqh, wql, nullptr, nullptr, q_gamma, q_beta, k_gamma, k_beta);

    // 2) tensor-core flash attention (writes bf16 hi/lo ao)
    attn_kernel<<<dim3(NUM_N/128, NUM_B*NUM_H), 256, ATTN_SMEM>>>(mask);

    // 3) output projection (+bias)
    mma_gemm<1><<<dim3(NUM_C/128, MTOT/128), 256, GEMM_SMEM>>>(
        aoh, aol, wph, wpl, b_proj, out, nullptr, nullptr, nullptr, nullptr);
}